// round 1
// baseline (speedup 1.0000x reference)
#include <cuda_runtime.h>
#include <math.h>

// ---------------------------------------------------------------------------
// Problem constants
// ---------------------------------------------------------------------------
constexpr int B     = 4;
constexpr int S     = 2048;
constexpr int EMBED = 2048;
constexpr int DC    = 512;   // D_COMPR
constexpr int DR    = 128;   // D_ROPE
constexpr int DCC   = DC - DR; // 384
constexpr int H     = 8;
constexpr int HD    = 64;    // head dim
constexpr int M     = B * S; // 8192 rows

// ---------------------------------------------------------------------------
// Scratch (device globals; no allocation allowed)
// ---------------------------------------------------------------------------
__device__ float g_cq [M * DC];
__device__ float g_ckv[M * DC];
__device__ float g_cqr[M * DR];
__device__ float g_ckr[M * DR];
__device__ float g_cqc[M * DCC];
__device__ float g_ckc[M * DCC];
__device__ float g_Q  [M * DC];
__device__ float g_K  [M * DC];
__device__ float g_V  [M * DC];
__device__ float g_O  [M * DC];

__device__ __forceinline__ float gelu_exact(float v) {
    return 0.5f * v * (1.0f + erff(v * 0.70710678118654752f));
}

// ---------------------------------------------------------------------------
// Generic tiled SGEMM: C[M,N] = act(A[M,K] @ W[N,K]^T + bias[N])
// grid = (N/64, M/64), block = 128 threads. 64x64x16 tiles, 4x8 microtiles.
// ---------------------------------------------------------------------------
template<bool GELU>
__global__ void gemm_kernel(const float* __restrict__ A,
                            const float* __restrict__ W,
                            const float* __restrict__ bias,
                            float* __restrict__ C,
                            int N, int K) {
    __shared__ float As[16][65];   // As[k][m]
    __shared__ float Ws[16][65];   // Ws[k][n]

    const int bm  = blockIdx.y * 64;
    const int bn  = blockIdx.x * 64;
    const int tid = threadIdx.x;          // 0..127
    const int ty  = tid >> 3;             // 0..15 -> row group (4 rows)
    const int tx  = tid & 7;              // 0..7  -> col group (8 cols)

    float acc[4][8];
    #pragma unroll
    for (int i = 0; i < 4; ++i)
        #pragma unroll
        for (int j = 0; j < 8; ++j) acc[i][j] = 0.0f;

    for (int k0 = 0; k0 < K; k0 += 16) {
        // load A tile: 64 rows x 16 k (1024 elems / 128 threads = 8 each)
        #pragma unroll
        for (int i = tid; i < 64 * 16; i += 128) {
            int m  = i >> 4;
            int kk = i & 15;
            As[kk][m] = A[(bm + m) * K + k0 + kk];
        }
        // load W tile: 64 n-rows x 16 k
        #pragma unroll
        for (int i = tid; i < 64 * 16; i += 128) {
            int n  = i >> 4;
            int kk = i & 15;
            Ws[kk][n] = W[(bn + n) * K + k0 + kk];
        }
        __syncthreads();

        #pragma unroll
        for (int kk = 0; kk < 16; ++kk) {
            float a[4], w[8];
            #pragma unroll
            for (int i = 0; i < 4; ++i) a[i] = As[kk][ty * 4 + i];
            #pragma unroll
            for (int j = 0; j < 8; ++j) w[j] = Ws[kk][tx * 8 + j];
            #pragma unroll
            for (int i = 0; i < 4; ++i)
                #pragma unroll
                for (int j = 0; j < 8; ++j)
                    acc[i][j] = fmaf(a[i], w[j], acc[i][j]);
        }
        __syncthreads();
    }

    #pragma unroll
    for (int i = 0; i < 4; ++i) {
        int m = bm + ty * 4 + i;
        #pragma unroll
        for (int j = 0; j < 8; ++j) {
            int n = bn + tx * 8 + j;
            float v = acc[i][j] + bias[n];
            if (GELU) v = gelu_exact(v);
            C[m * N + n] = v;
        }
    }
}

// ---------------------------------------------------------------------------
// Build Q or K: out[m, 0:384] = cc, out[m, 384:512] = rope(cr), then GELU(all)
// ---------------------------------------------------------------------------
__global__ void build_qk_kernel(const float* __restrict__ cc,   // [M,384]
                                const float* __restrict__ cr,   // [M,128]
                                float* __restrict__ out) {      // [M,512]
    int idx = blockIdx.x * blockDim.x + threadIdx.x;
    if (idx >= M * DC) return;
    int m = idx / DC;
    int c = idx - m * DC;
    float v;
    if (c < DCC) {
        v = cc[m * DCC + c];
    } else {
        int j = c - DCC;          // 0..127 within rope block
        int i = j & 63;           // freq index
        int s = m % S;            // sequence position
        // inv_freq[i] = 10000^(-i/64)
        float invf = expf(-(float)i * (9.210340371976184f / 64.0f)); // ln(10000)
        float ang  = (float)s * invf;
        float cv = cosf(ang), sv = sinf(ang);
        float xj  = cr[m * DR + j];
        float rot = (j < 64) ? -cr[m * DR + j + 64] : cr[m * DR + j - 64];
        v = xj * cv + rot * sv;
    }
    out[idx] = gelu_exact(v);
}

// ---------------------------------------------------------------------------
// Flash attention (causal). grid = (S/64, H, B), block = 128 threads.
// 64-query tile per block; streams 64-key tiles with online softmax.
// Q,K,V,O are [M, 512] with head h at columns [h*64, h*64+64).
// ---------------------------------------------------------------------------
constexpr int ATTN_SMEM_FLOATS = 4 * 64 * 65 + 3 * 64;
constexpr int ATTN_SMEM_BYTES  = ATTN_SMEM_FLOATS * 4;

__global__ void attn_kernel(const float* __restrict__ Q,
                            const float* __restrict__ K,
                            const float* __restrict__ V,
                            float* __restrict__ O) {
    extern __shared__ float sm[];
    float* Qs   = sm;                 // [64][65]
    float* Ks   = Qs + 64 * 65;       // [64][65]
    float* Vs   = Ks + 64 * 65;       // [64][65]
    float* Ps   = Vs + 64 * 65;       // [64][65] scores/probs
    float* mrow = Ps + 64 * 65;       // [64]
    float* lrow = mrow + 64;          // [64]
    float* arow = lrow + 64;          // [64]

    const int qt = blockIdx.x;
    const int h  = blockIdx.y;
    const int b  = blockIdx.z;
    const int q0 = qt * 64;
    const int tid = threadIdx.x;
    const int ty  = tid >> 3;         // 0..15
    const int tx  = tid & 7;          // 0..7
    const float scale = 0.125f;       // 1/sqrt(64)

    // load Q tile
    for (int i = tid; i < 64 * 64; i += 128) {
        int r = i >> 6, c = i & 63;
        Qs[r * 65 + c] = Q[(size_t)(b * S + q0 + r) * DC + h * HD + c];
    }
    if (tid < 64) { mrow[tid] = -INFINITY; lrow[tid] = 0.0f; }

    float acc[4][8];
    #pragma unroll
    for (int i = 0; i < 4; ++i)
        #pragma unroll
        for (int j = 0; j < 8; ++j) acc[i][j] = 0.0f;

    for (int kt = 0; kt <= qt; ++kt) {
        const int k0 = kt * 64;
        __syncthreads();   // protect Ks/Vs from previous iteration's readers
        for (int i = tid; i < 64 * 64; i += 128) {
            int r = i >> 6, c = i & 63;
            size_t row = (size_t)(b * S + k0 + r) * DC + h * HD + c;
            Ks[r * 65 + (i & 63)] = K[row];
            Vs[r * 65 + (i & 63)] = V[row];
        }
        __syncthreads();

        // ----- scores: Ps = Qs @ Ks^T * scale, causal-masked -----
        float s_[4][8];
        #pragma unroll
        for (int i = 0; i < 4; ++i)
            #pragma unroll
            for (int j = 0; j < 8; ++j) s_[i][j] = 0.0f;
        #pragma unroll 4
        for (int kk = 0; kk < 64; ++kk) {
            float a[4], w[8];
            #pragma unroll
            for (int i = 0; i < 4; ++i) a[i] = Qs[(ty * 4 + i) * 65 + kk];
            #pragma unroll
            for (int j = 0; j < 8; ++j) w[j] = Ks[(tx * 8 + j) * 65 + kk];
            #pragma unroll
            for (int i = 0; i < 4; ++i)
                #pragma unroll
                for (int j = 0; j < 8; ++j)
                    s_[i][j] = fmaf(a[i], w[j], s_[i][j]);
        }
        #pragma unroll
        for (int i = 0; i < 4; ++i) {
            int qg = q0 + ty * 4 + i;
            #pragma unroll
            for (int j = 0; j < 8; ++j) {
                int kg = k0 + tx * 8 + j;
                float v = s_[i][j] * scale;
                Ps[(ty * 4 + i) * 65 + tx * 8 + j] = (kg > qg) ? -INFINITY : v;
            }
        }
        __syncthreads();

        // ----- online softmax row update (one thread per row) -----
        if (tid < 64) {
            int r = tid;
            float mo = mrow[r];
            float mx = mo;
            #pragma unroll 8
            for (int c = 0; c < 64; ++c) mx = fmaxf(mx, Ps[r * 65 + c]);
            float a = expf(mo - mx);       // 0 on first tile (mo=-inf, mx finite)
            float sum = 0.0f;
            #pragma unroll 8
            for (int c = 0; c < 64; ++c) {
                float p = expf(Ps[r * 65 + c] - mx);
                Ps[r * 65 + c] = p;
                sum += p;
            }
            mrow[r] = mx;
            lrow[r] = lrow[r] * a + sum;
            arow[r] = a;
        }
        __syncthreads();

        // ----- O update: acc = acc*alpha + P @ Vs -----
        #pragma unroll
        for (int i = 0; i < 4; ++i) {
            float a = arow[ty * 4 + i];
            #pragma unroll
            for (int j = 0; j < 8; ++j) acc[i][j] *= a;
        }
        #pragma unroll 4
        for (int kk = 0; kk < 64; ++kk) {
            float p[4], vv[8];
            #pragma unroll
            for (int i = 0; i < 4; ++i) p[i] = Ps[(ty * 4 + i) * 65 + kk];
            #pragma unroll
            for (int j = 0; j < 8; ++j) vv[j] = Vs[kk * 65 + tx * 8 + j];
            #pragma unroll
            for (int i = 0; i < 4; ++i)
                #pragma unroll
                for (int j = 0; j < 8; ++j)
                    acc[i][j] = fmaf(p[i], vv[j], acc[i][j]);
        }
    }

    __syncthreads();
    #pragma unroll
    for (int i = 0; i < 4; ++i) {
        int r = ty * 4 + i;
        float inv = 1.0f / lrow[r];
        size_t row = (size_t)(b * S + q0 + r) * DC + h * HD;
        #pragma unroll
        for (int j = 0; j < 8; ++j)
            O[row + tx * 8 + j] = acc[i][j] * inv;
    }
}

// ---------------------------------------------------------------------------
// Launch
// ---------------------------------------------------------------------------
extern "C" void kernel_launch(void* const* d_in, const int* in_sizes, int n_in,
                              void* d_out, int out_size) {
    const float* x     = (const float*)d_in[0];
    const float* CQ_w  = (const float*)d_in[1];
    const float* CQ_b  = (const float*)d_in[2];
    const float* CQC_w = (const float*)d_in[3];
    const float* CQC_b = (const float*)d_in[4];
    const float* CQR_w = (const float*)d_in[5];
    const float* CQR_b = (const float*)d_in[6];
    const float* CKV_w = (const float*)d_in[7];
    const float* CKV_b = (const float*)d_in[8];
    const float* CKR_w = (const float*)d_in[9];
    const float* CKR_b = (const float*)d_in[10];
    const float* CKC_w = (const float*)d_in[11];
    const float* CKC_b = (const float*)d_in[12];
    const float* CV_w  = (const float*)d_in[13];
    const float* CV_b  = (const float*)d_in[14];
    const float* OUT_w = (const float*)d_in[15];
    const float* OUT_b = (const float*)d_in[16];
    float* out = (float*)d_out;

    float *cq, *ckv, *cqr, *ckr, *cqc, *ckc, *Qb, *Kb, *Vb, *Ob;
    cudaGetSymbolAddress((void**)&cq,  g_cq);
    cudaGetSymbolAddress((void**)&ckv, g_ckv);
    cudaGetSymbolAddress((void**)&cqr, g_cqr);
    cudaGetSymbolAddress((void**)&ckr, g_ckr);
    cudaGetSymbolAddress((void**)&cqc, g_cqc);
    cudaGetSymbolAddress((void**)&ckc, g_ckc);
    cudaGetSymbolAddress((void**)&Qb,  g_Q);
    cudaGetSymbolAddress((void**)&Kb,  g_K);
    cudaGetSymbolAddress((void**)&Vb,  g_V);
    cudaGetSymbolAddress((void**)&Ob,  g_O);

    cudaFuncSetAttribute(attn_kernel,
                         cudaFuncAttributeMaxDynamicSharedMemorySize,
                         ATTN_SMEM_BYTES);

    dim3 blk(128);
    dim3 gM64(0, M / 64);

    // cq = gelu(x @ CQ_w^T + b)          [M,512]
    gemm_kernel<true ><<<dim3(DC    / 64, M / 64), blk>>>(x,   CQ_w,  CQ_b,  cq,  DC,    EMBED);
    // ckv = gelu(x @ CKV_w^T + b)        [M,512]
    gemm_kernel<true ><<<dim3(DC    / 64, M / 64), blk>>>(x,   CKV_w, CKV_b, ckv, DC,    EMBED);
    // cqr = x @ CQR_w^T + b              [M,128]
    gemm_kernel<false><<<dim3(DR    / 64, M / 64), blk>>>(x,   CQR_w, CQR_b, cqr, DR,    EMBED);
    // ckr = x @ CKR_w^T + b              [M,128]
    gemm_kernel<false><<<dim3(DR    / 64, M / 64), blk>>>(x,   CKR_w, CKR_b, ckr, DR,    EMBED);
    // cqc = cq @ CQC_w^T + b             [M,384]
    gemm_kernel<false><<<dim3(DCC   / 64, M / 64), blk>>>(cq,  CQC_w, CQC_b, cqc, DCC,   DC);
    // ckc = ckv @ CKC_w^T + b            [M,384]
    gemm_kernel<false><<<dim3(DCC   / 64, M / 64), blk>>>(ckv, CKC_w, CKC_b, ckc, DCC,   DC);
    // V = ckv @ CV_w^T + b               [M,512]
    gemm_kernel<false><<<dim3(DC    / 64, M / 64), blk>>>(ckv, CV_w,  CV_b,  Vb,  DC,    DC);

    // Q = gelu(concat(cqc, rope(cqr))),  K = gelu(concat(ckc, rope(ckr)))
    int nelem = M * DC;
    int nblk  = (nelem + 255) / 256;
    build_qk_kernel<<<nblk, 256>>>(cqc, cqr, Qb);
    build_qk_kernel<<<nblk, 256>>>(ckc, ckr, Kb);

    // causal flash attention
    attn_kernel<<<dim3(S / 64, H, B), blk, ATTN_SMEM_BYTES>>>(Qb, Kb, Vb, Ob);

    // out = O @ OUT_w^T + b              [M,2048]
    gemm_kernel<false><<<dim3(EMBED / 64, M / 64), blk>>>(Ob, OUT_w, OUT_b, out, EMBED, DC);
}

// round 2
// speedup vs baseline: 2.7747x; 2.7747x over previous
#include <cuda_runtime.h>
#include <math.h>

// ---------------------------------------------------------------------------
// Problem constants
// ---------------------------------------------------------------------------
constexpr int B     = 4;
constexpr int S     = 2048;
constexpr int EMBED = 2048;
constexpr int DC    = 512;     // D_COMPR
constexpr int DR    = 128;     // D_ROPE
constexpr int DCC   = DC - DR; // 384
constexpr int H     = 8;
constexpr int HD    = 64;      // head dim
constexpr int M     = B * S;   // 8192 rows

// ---------------------------------------------------------------------------
// Scratch (device globals; allocation is forbidden)
// ---------------------------------------------------------------------------
__device__ float g_wcat[1024 * 2048];   // [CQ_w; CKV_w]
__device__ float g_wqr [256 * 2048];    // [CQR_w; CKR_w]
__device__ float g_bcat[1024];
__device__ float g_bqr [256];
__device__ float g_cqkv[M * 1024];      // cols 0-511: cq, 512-1023: ckv
__device__ float g_qr  [M * 256];       // cols 0-127: cqr, 128-255: ckr
__device__ float g_cc  [2 * M * DCC];   // [0]: cqc, [1]: ckc
__device__ float g_Q   [M * DC];
__device__ float g_K   [M * DC];
__device__ float g_V   [M * DC];
__device__ float g_O   [M * DC];

__device__ __forceinline__ float gelu_exact(float v) {
    return 0.5f * v * (1.0f + erff(v * 0.70710678118654752f));
}

// ---------------------------------------------------------------------------
// concat copy: dst[0:n0) = s0, dst[n0:n0+n1) = s1
// ---------------------------------------------------------------------------
__global__ void concat2(float* __restrict__ dst,
                        const float* __restrict__ s0,
                        const float* __restrict__ s1, int n0, int n1) {
    int i = blockIdx.x * blockDim.x + threadIdx.x;
    if (i < n0) dst[i] = s0[i];
    else if (i < n0 + n1) dst[i] = s1[i - n0];
}

// ---------------------------------------------------------------------------
// SGEMM: C[M,N] = act(A[M,K] @ W[N,K]^T + bias[N])
// 128x128 block tile, BK=16, 256 threads, 8x8 microtile (4-wide fragments),
// float4 global loads, double-buffered smem. blockIdx.z selects pointer set.
// Requires: M%128==0, N%128==0, K%16==0.
// ---------------------------------------------------------------------------
template<bool GELU>
__global__ void sgemm(const float* __restrict__ A0, const float* __restrict__ A1,
                      const float* __restrict__ W0, const float* __restrict__ W1,
                      const float* __restrict__ b0, const float* __restrict__ b1,
                      float* __restrict__ C0, float* __restrict__ C1,
                      int N, int K, int lda, int ldc) {
    const float* A    = blockIdx.z ? A1 : A0;
    const float* W    = blockIdx.z ? W1 : W0;
    const float* bias = blockIdx.z ? b1 : b0;
    float*       C    = blockIdx.z ? C1 : C0;

    __shared__ float As[2][16][128];
    __shared__ float Ws[2][16][128];

    const int tid = threadIdx.x;
    const int bm  = blockIdx.y * 128;
    const int bn  = blockIdx.x * 128;

    // global load mapping: 2 float4 per array per thread
    const int lr = tid >> 2;            // 0..63
    const int lk = (tid & 3) * 4;       // 0,4,8,12

    // compute mapping
    const int tx = tid & 15;            // 0..15
    const int ty = tid >> 4;            // 0..15

    const float* Aptr = A + (size_t)(bm + lr) * lda + lk;
    const float* Wptr = W + (size_t)(bn + lr) * K + lk;

    float4 pa0 = *(const float4*)(Aptr);
    float4 pa1 = *(const float4*)(Aptr + (size_t)64 * lda);
    float4 pw0 = *(const float4*)(Wptr);
    float4 pw1 = *(const float4*)(Wptr + (size_t)64 * K);

    float acc[8][8];
    #pragma unroll
    for (int i = 0; i < 8; ++i)
        #pragma unroll
        for (int j = 0; j < 8; ++j) acc[i][j] = 0.0f;

    // stage 0 store
    As[0][lk+0][lr] = pa0.x; As[0][lk+1][lr] = pa0.y;
    As[0][lk+2][lr] = pa0.z; As[0][lk+3][lr] = pa0.w;
    As[0][lk+0][lr+64] = pa1.x; As[0][lk+1][lr+64] = pa1.y;
    As[0][lk+2][lr+64] = pa1.z; As[0][lk+3][lr+64] = pa1.w;
    Ws[0][lk+0][lr] = pw0.x; Ws[0][lk+1][lr] = pw0.y;
    Ws[0][lk+2][lr] = pw0.z; Ws[0][lk+3][lr] = pw0.w;
    Ws[0][lk+0][lr+64] = pw1.x; Ws[0][lk+1][lr+64] = pw1.y;
    Ws[0][lk+2][lr+64] = pw1.z; Ws[0][lk+3][lr+64] = pw1.w;
    __syncthreads();

    const int KT = K >> 4;
    int buf = 0;
    for (int kt = 0; kt < KT; ++kt) {
        if (kt + 1 < KT) {
            const float* Ap = Aptr + (kt + 1) * 16;
            const float* Wp = Wptr + (kt + 1) * 16;
            pa0 = *(const float4*)(Ap);
            pa1 = *(const float4*)(Ap + (size_t)64 * lda);
            pw0 = *(const float4*)(Wp);
            pw1 = *(const float4*)(Wp + (size_t)64 * K);
        }

        const float (*Ab)[128] = As[buf];
        const float (*Wb)[128] = Ws[buf];
        #pragma unroll
        for (int kk = 0; kk < 16; ++kk) {
            float4 a0 = *(const float4*)&Ab[kk][ty * 4];
            float4 a1 = *(const float4*)&Ab[kk][64 + ty * 4];
            float4 w0 = *(const float4*)&Wb[kk][tx * 4];
            float4 w1 = *(const float4*)&Wb[kk][64 + tx * 4];
            float a[8] = {a0.x,a0.y,a0.z,a0.w,a1.x,a1.y,a1.z,a1.w};
            float w[8] = {w0.x,w0.y,w0.z,w0.w,w1.x,w1.y,w1.z,w1.w};
            #pragma unroll
            for (int i = 0; i < 8; ++i)
                #pragma unroll
                for (int j = 0; j < 8; ++j)
                    acc[i][j] = fmaf(a[i], w[j], acc[i][j]);
        }

        if (kt + 1 < KT) {
            int nb = buf ^ 1;
            As[nb][lk+0][lr] = pa0.x; As[nb][lk+1][lr] = pa0.y;
            As[nb][lk+2][lr] = pa0.z; As[nb][lk+3][lr] = pa0.w;
            As[nb][lk+0][lr+64] = pa1.x; As[nb][lk+1][lr+64] = pa1.y;
            As[nb][lk+2][lr+64] = pa1.z; As[nb][lk+3][lr+64] = pa1.w;
            Ws[nb][lk+0][lr] = pw0.x; Ws[nb][lk+1][lr] = pw0.y;
            Ws[nb][lk+2][lr] = pw0.z; Ws[nb][lk+3][lr] = pw0.w;
            Ws[nb][lk+0][lr+64] = pw1.x; Ws[nb][lk+1][lr+64] = pw1.y;
            Ws[nb][lk+2][lr+64] = pw1.z; Ws[nb][lk+3][lr+64] = pw1.w;
            __syncthreads();
            buf = nb;
        }
    }

    // epilogue
    float bv[8];
    #pragma unroll
    for (int j = 0; j < 8; ++j) {
        int col = (j < 4) ? (tx * 4 + j) : (64 + tx * 4 + j - 4);
        bv[j] = bias[bn + col];
    }
    #pragma unroll
    for (int i = 0; i < 8; ++i) {
        int row = (i < 4) ? (ty * 4 + i) : (64 + ty * 4 + i - 4);
        int m = bm + row;
        float o[8];
        #pragma unroll
        for (int j = 0; j < 8; ++j) {
            float v = acc[i][j] + bv[j];
            o[j] = GELU ? gelu_exact(v) : v;
        }
        *(float4*)&C[(size_t)m * ldc + bn + tx * 4]      = make_float4(o[0],o[1],o[2],o[3]);
        *(float4*)&C[(size_t)m * ldc + bn + 64 + tx * 4] = make_float4(o[4],o[5],o[6],o[7]);
    }
}

// ---------------------------------------------------------------------------
// Build Q or K: out[m,0:384]=cc, out[m,384:512]=rope(cr), then GELU(all)
// cr = g_qr[m*256 + qroff + j]
// ---------------------------------------------------------------------------
__global__ void build_qk(const float* __restrict__ cc,
                         const float* __restrict__ qr, int qroff,
                         float* __restrict__ out) {
    int idx = blockIdx.x * blockDim.x + threadIdx.x;
    if (idx >= M * DC) return;
    int m = idx >> 9;        // /512
    int c = idx & 511;
    float v;
    if (c < DCC) {
        v = cc[m * DCC + c];
    } else {
        int j = c - DCC;     // 0..127
        int i = j & 63;
        int s = m & (S - 1); // m % S
        float invf = expf(-(float)i * (9.2103403719761836f / 64.0f)); // ln(1e4)
        float ang  = (float)s * invf;
        float sv, cv;
        sincosf(ang, &sv, &cv);
        float xj  = qr[m * 256 + qroff + j];
        float rot = (j < 64) ? -qr[m * 256 + qroff + j + 64]
                             :  qr[m * 256 + qroff + j - 64];
        v = xj * cv + rot * sv;
    }
    out[idx] = gelu_exact(v);
}

// ---------------------------------------------------------------------------
// Flash attention (causal). grid = (S/128, H, B), 256 threads.
// 128-query x 64-key tiles, online softmax. 8x4 microtile per thread.
// ---------------------------------------------------------------------------
constexpr int ATTN_SMEM_FLOATS = 128*65 + 64*65 + 64*64 + 128*65 + 3*128;
constexpr int ATTN_SMEM_BYTES  = ATTN_SMEM_FLOATS * 4;

__global__ void attn_kernel(const float* __restrict__ Q,
                            const float* __restrict__ K,
                            const float* __restrict__ V,
                            float* __restrict__ O) {
    extern __shared__ float sm[];
    float* Qs   = sm;                    // [128][65]
    float* Ks   = Qs + 128 * 65;         // [64][65]
    float* Vs   = Ks + 64 * 65;          // [64][64]
    float* Ps   = Vs + 64 * 64;          // [128][65]
    float* mrow = Ps + 128 * 65;         // [128]
    float* lrow = mrow + 128;            // [128]
    float* arow = lrow + 128;            // [128]

    const int qt = blockIdx.x;
    const int h  = blockIdx.y;
    const int b  = blockIdx.z;
    const int q0 = qt * 128;
    const int tid = threadIdx.x;
    const int tx  = tid & 15;
    const int ty  = tid >> 4;
    const float scale = 0.125f;

    const size_t base = (size_t)b * S * DC + h * HD;

    // row indices of this thread's 8 output rows
    int r8[8];
    #pragma unroll
    for (int i = 0; i < 8; ++i)
        r8[i] = (i < 4) ? (ty * 4 + i) : (64 + ty * 4 + i - 4);

    // load Q tile (scalar smem stores into stride-65 rows)
    {
        int r  = tid >> 4;
        int c4 = (tid & 15) * 4;
        for (int rr = r; rr < 128; rr += 16) {
            float4 q4 = *(const float4*)&Q[base + (size_t)(q0 + rr) * DC + c4];
            Qs[rr * 65 + c4 + 0] = q4.x; Qs[rr * 65 + c4 + 1] = q4.y;
            Qs[rr * 65 + c4 + 2] = q4.z; Qs[rr * 65 + c4 + 3] = q4.w;
        }
    }
    if (tid < 128) { mrow[tid] = -INFINITY; lrow[tid] = 0.0f; }

    float acc[8][4];
    #pragma unroll
    for (int i = 0; i < 8; ++i)
        #pragma unroll
        for (int j = 0; j < 4; ++j) acc[i][j] = 0.0f;

    const int kt_end = 2 * qt + 1;
    for (int kt = 0; kt <= kt_end; ++kt) {
        const int k0 = kt * 64;
        const bool do_mask = (k0 + 63 > q0);

        __syncthreads();   // prior Ps/Vs readers done; Qs ready (iter 0)

        // load K/V tiles
        {
            int r  = tid >> 4;
            int c4 = (tid & 15) * 4;
            for (int rr = r; rr < 64; rr += 16) {
                size_t row = base + (size_t)(k0 + rr) * DC + c4;
                float4 k4 = *(const float4*)&K[row];
                float4 v4 = *(const float4*)&V[row];
                Ks[rr * 65 + c4 + 0] = k4.x; Ks[rr * 65 + c4 + 1] = k4.y;
                Ks[rr * 65 + c4 + 2] = k4.z; Ks[rr * 65 + c4 + 3] = k4.w;
                *(float4*)&Vs[rr * 64 + c4] = v4;
            }
        }
        __syncthreads();

        // scores: s = Qs @ Ks^T
        float s_[8][4];
        #pragma unroll
        for (int i = 0; i < 8; ++i)
            #pragma unroll
            for (int j = 0; j < 4; ++j) s_[i][j] = 0.0f;

        #pragma unroll 4
        for (int kk = 0; kk < 64; ++kk) {
            float a[8], w[4];
            #pragma unroll
            for (int i = 0; i < 8; ++i) a[i] = Qs[r8[i] * 65 + kk];
            #pragma unroll
            for (int j = 0; j < 4; ++j) w[j] = Ks[(tx * 4 + j) * 65 + kk];
            #pragma unroll
            for (int i = 0; i < 8; ++i)
                #pragma unroll
                for (int j = 0; j < 4; ++j)
                    s_[i][j] = fmaf(a[i], w[j], s_[i][j]);
        }

        #pragma unroll
        for (int i = 0; i < 8; ++i) {
            int qg = q0 + r8[i];
            #pragma unroll
            for (int j = 0; j < 4; ++j) {
                int kg = k0 + tx * 4 + j;
                float v = s_[i][j] * scale;
                if (do_mask && kg > qg) v = -INFINITY;
                Ps[r8[i] * 65 + tx * 4 + j] = v;
            }
        }
        __syncthreads();

        // online softmax (one thread per row)
        if (tid < 128) {
            int r = tid;
            float mo = mrow[r];
            float mx = mo;
            #pragma unroll 8
            for (int c = 0; c < 64; ++c) mx = fmaxf(mx, Ps[r * 65 + c]);
            float a = __expf(mo - mx);
            float sum = 0.0f;
            #pragma unroll 8
            for (int c = 0; c < 64; ++c) {
                float p = __expf(Ps[r * 65 + c] - mx);
                Ps[r * 65 + c] = p;
                sum += p;
            }
            mrow[r] = mx;
            lrow[r] = lrow[r] * a + sum;
            arow[r] = a;
        }
        __syncthreads();

        // acc = acc * alpha + P @ Vs
        #pragma unroll
        for (int i = 0; i < 8; ++i) {
            float a = arow[r8[i]];
            #pragma unroll
            for (int j = 0; j < 4; ++j) acc[i][j] *= a;
        }
        #pragma unroll 4
        for (int kk = 0; kk < 64; ++kk) {
            float p[8];
            #pragma unroll
            for (int i = 0; i < 8; ++i) p[i] = Ps[r8[i] * 65 + kk];
            float4 v4 = *(const float4*)&Vs[kk * 64 + tx * 4];
            float w[4] = {v4.x, v4.y, v4.z, v4.w};
            #pragma unroll
            for (int i = 0; i < 8; ++i)
                #pragma unroll
                for (int j = 0; j < 4; ++j)
                    acc[i][j] = fmaf(p[i], w[j], acc[i][j]);
        }
    }

    __syncthreads();
    #pragma unroll
    for (int i = 0; i < 8; ++i) {
        float inv = 1.0f / lrow[r8[i]];
        float4 o = make_float4(acc[i][0]*inv, acc[i][1]*inv,
                               acc[i][2]*inv, acc[i][3]*inv);
        *(float4*)&O[base + (size_t)(q0 + r8[i]) * DC + tx * 4] = o;
    }
}

// ---------------------------------------------------------------------------
// Launch
// ---------------------------------------------------------------------------
extern "C" void kernel_launch(void* const* d_in, const int* in_sizes, int n_in,
                              void* d_out, int out_size) {
    const float* x     = (const float*)d_in[0];
    const float* CQ_w  = (const float*)d_in[1];
    const float* CQ_b  = (const float*)d_in[2];
    const float* CQC_w = (const float*)d_in[3];
    const float* CQC_b = (const float*)d_in[4];
    const float* CQR_w = (const float*)d_in[5];
    const float* CQR_b = (const float*)d_in[6];
    const float* CKV_w = (const float*)d_in[7];
    const float* CKV_b = (const float*)d_in[8];
    const float* CKR_w = (const float*)d_in[9];
    const float* CKR_b = (const float*)d_in[10];
    const float* CKC_w = (const float*)d_in[11];
    const float* CKC_b = (const float*)d_in[12];
    const float* CV_w  = (const float*)d_in[13];
    const float* CV_b  = (const float*)d_in[14];
    const float* OUT_w = (const float*)d_in[15];
    const float* OUT_b = (const float*)d_in[16];
    float* out = (float*)d_out;

    float *wcat, *wqr, *bcat, *bqr, *cqkv, *qr, *cc, *Qb, *Kb, *Vb, *Ob;
    cudaGetSymbolAddress((void**)&wcat, g_wcat);
    cudaGetSymbolAddress((void**)&wqr,  g_wqr);
    cudaGetSymbolAddress((void**)&bcat, g_bcat);
    cudaGetSymbolAddress((void**)&bqr,  g_bqr);
    cudaGetSymbolAddress((void**)&cqkv, g_cqkv);
    cudaGetSymbolAddress((void**)&qr,   g_qr);
    cudaGetSymbolAddress((void**)&cc,   g_cc);
    cudaGetSymbolAddress((void**)&Qb,   g_Q);
    cudaGetSymbolAddress((void**)&Kb,   g_K);
    cudaGetSymbolAddress((void**)&Vb,   g_V);
    cudaGetSymbolAddress((void**)&Ob,   g_O);

    cudaFuncSetAttribute(attn_kernel,
                         cudaFuncAttributeMaxDynamicSharedMemorySize,
                         ATTN_SMEM_BYTES);

    // weight/bias concats
    {
        int n = 512 * 2048;
        concat2<<<(2*n + 255)/256, 256>>>(wcat, CQ_w, CKV_w, n, n);
        int nq = 128 * 2048;
        concat2<<<(2*nq + 255)/256, 256>>>(wqr, CQR_w, CKR_w, nq, nq);
        concat2<<<(1024 + 255)/256, 256>>>(bcat, CQ_b, CKV_b, 512, 512);
        concat2<<<(256 + 255)/256, 256>>>(bqr, CQR_b, CKR_b, 128, 128);
    }

    dim3 blk(256);
    // cq|ckv = gelu(x @ [CQ_w;CKV_w]^T + b)    [M,1024]
    sgemm<true ><<<dim3(1024/128, M/128, 1), blk>>>(x, x, wcat, wcat, bcat, bcat,
                                                    cqkv, cqkv, 1024, EMBED, EMBED, 1024);
    // cqr|ckr = x @ [CQR_w;CKR_w]^T + b        [M,256]
    sgemm<false><<<dim3(256/128, M/128, 1), blk>>>(x, x, wqr, wqr, bqr, bqr,
                                                   qr, qr, 256, EMBED, EMBED, 256);
    // z=0: cqc = cq @ CQC_w^T; z=1: ckc = ckv @ CKC_w^T   [M,384] each
    sgemm<false><<<dim3(DCC/128, M/128, 2), blk>>>(cqkv, cqkv + 512,
                                                   CQC_w, CKC_w, CQC_b, CKC_b,
                                                   cc, cc + (size_t)M * DCC,
                                                   DCC, DC, 1024, DCC);
    // V = ckv @ CV_w^T + b                      [M,512]
    sgemm<false><<<dim3(DC/128, M/128, 1), blk>>>(cqkv + 512, cqkv + 512,
                                                  CV_w, CV_w, CV_b, CV_b,
                                                  Vb, Vb, DC, DC, 1024, DC);

    // Q/K build (concat + rope + gelu)
    int nelem = M * DC;
    int nblk  = (nelem + 255) / 256;
    build_qk<<<nblk, 256>>>(cc, qr, 0, Qb);
    build_qk<<<nblk, 256>>>(cc + (size_t)M * DCC, qr, 128, Kb);

    // causal flash attention
    attn_kernel<<<dim3(S/128, H, B), blk, ATTN_SMEM_BYTES>>>(Qb, Kb, Vb, Ob);

    // out = O @ OUT_w^T + b                     [M,2048]
    sgemm<false><<<dim3(EMBED/128, M/128, 1), blk>>>(Ob, Ob, OUT_w, OUT_w,
                                                     OUT_b, OUT_b, out, out,
                                                     EMBED, DC, DC, EMBED);
}

// round 4
// speedup vs baseline: 4.1694x; 1.5026x over previous
#include <cuda_runtime.h>
#include <cuda_bf16.h>
#include <math.h>
#include <stdint.h>

// ---------------------------------------------------------------------------
// Problem constants
// ---------------------------------------------------------------------------
constexpr int B     = 4;
constexpr int S     = 2048;
constexpr int EMBED = 2048;
constexpr int DC    = 512;     // D_COMPR
constexpr int DR    = 128;     // D_ROPE
constexpr int DCC   = DC - DR; // 384
constexpr int H     = 8;
constexpr int HD    = 64;      // head dim
constexpr int M     = B * S;   // 8192 rows

// weight-plane offsets (elements) inside g_wh / g_wl
constexpr size_t OFF_Q   = 0;                       // 512*2048
constexpr size_t OFF_KV  = OFF_Q   + 512 * 2048;
constexpr size_t OFF_QR  = OFF_KV  + 512 * 2048;    // 128*2048
constexpr size_t OFF_KR  = OFF_QR  + 128 * 2048;
constexpr size_t OFF_QC  = OFF_KR  + 128 * 2048;    // 384*512
constexpr size_t OFF_KC  = OFF_QC  + 384 * 512;
constexpr size_t OFF_V   = OFF_KC  + 384 * 512;     // 512*512
constexpr size_t OFF_OUT = OFF_V   + 512 * 512;     // 2048*512
constexpr size_t W_TOTAL = OFF_OUT + 2048 * 512;

// ---------------------------------------------------------------------------
// Scratch (device globals; allocation is forbidden)
// ---------------------------------------------------------------------------
__device__ __align__(16) __nv_bfloat16 g_xh[(size_t)M * 2048];
__device__ __align__(16) __nv_bfloat16 g_xl[(size_t)M * 2048];
__device__ __align__(16) __nv_bfloat16 g_wh[W_TOTAL];
__device__ __align__(16) __nv_bfloat16 g_wl[W_TOTAL];
__device__ __align__(16) __nv_bfloat16 g_cqkvh[(size_t)M * 1024]; // cq|ckv planes
__device__ __align__(16) __nv_bfloat16 g_cqkvl[(size_t)M * 1024];
__device__ __align__(16) __nv_bfloat16 g_oh[(size_t)M * 512];
__device__ __align__(16) __nv_bfloat16 g_ol[(size_t)M * 512];
__device__ float g_qr [M * 256];       // cols 0-127: cqr, 128-255: ckr
__device__ float g_cc [2 * M * DCC];   // [0]: cqc, [1]: ckc
__device__ float g_Q  [M * DC];
__device__ float g_K  [M * DC];
__device__ float g_V  [M * DC];

__device__ __forceinline__ float gelu_exact(float v) {
    return 0.5f * v * (1.0f + erff(v * 0.70710678118654752f));
}

// fp32 pair -> bf16x2 hi + bf16x2 lo residual
__device__ __forceinline__ void cvt_pair(float e0, float e1,
                                         uint32_t& h, uint32_t& l) {
    asm("cvt.rn.bf16x2.f32 %0, %1, %2;" : "=r"(h) : "f"(e1), "f"(e0));
    float h0 = __uint_as_float(h << 16);
    float h1 = __uint_as_float(h & 0xFFFF0000u);
    asm("cvt.rn.bf16x2.f32 %0, %1, %2;" : "=r"(l) : "f"(e1 - h1), "f"(e0 - h0));
}

__device__ __forceinline__ uint32_t smem_u32(const void* p) {
    uint32_t a;
    asm("{ .reg .u64 t; cvta.to.shared.u64 t, %1; cvt.u32.u64 %0, t; }"
        : "=r"(a) : "l"(p));
    return a;
}

#define CP16(dst, src) \
    asm volatile("cp.async.cg.shared.global [%0], [%1], 16;" \
                 :: "r"(dst), "l"(src) : "memory")
#define CP_COMMIT() asm volatile("cp.async.commit_group;" ::: "memory")
#define CP_WAIT1()  asm volatile("cp.async.wait_group 1;" ::: "memory")

#define LDSM4(r0, r1, r2, r3, addr) \
    asm volatile("ldmatrix.sync.aligned.m8n8.x4.shared.b16 {%0,%1,%2,%3}, [%4];" \
                 : "=r"(r0), "=r"(r1), "=r"(r2), "=r"(r3) : "r"(addr))

#define MMA_BF16(d, a, b) \
    asm volatile("mma.sync.aligned.m16n8k16.row.col.f32.bf16.bf16.f32 " \
                 "{%0,%1,%2,%3},{%4,%5,%6,%7},{%8,%9},{%0,%1,%2,%3};" \
                 : "+f"((d)[0]), "+f"((d)[1]), "+f"((d)[2]), "+f"((d)[3]) \
                 : "r"((a)[0]), "r"((a)[1]), "r"((a)[2]), "r"((a)[3]), \
                   "r"((b)[0]), "r"((b)[1]))

// ---------------------------------------------------------------------------
// fp32 -> bf16 hi/lo planes (n must be divisible by 4)
// ---------------------------------------------------------------------------
__global__ void cvt_planes(const float* __restrict__ src,
                           __nv_bfloat16* __restrict__ h,
                           __nv_bfloat16* __restrict__ l, int n4) {
    int i = blockIdx.x * blockDim.x + threadIdx.x;
    if (i >= n4) return;
    float4 v = ((const float4*)src)[i];
    uint32_t h0, h1, l0, l1;
    cvt_pair(v.x, v.y, h0, l0);
    cvt_pair(v.z, v.w, h1, l1);
    ((uint2*)h)[i] = make_uint2(h0, h1);
    ((uint2*)l)[i] = make_uint2(l0, l1);
}

// ---------------------------------------------------------------------------
// Tensor-core GEMM via mma.sync (bf16 hi/lo split, fp32 accumulate)
// C[M,N] = act(A[M,K] @ W[N,K]^T + bias[N]);  D = Ah*Wh + Ah*Wl + Al*Wh
// 128x128 CTA tile, BK=32, 256 threads (8 warps: 2m x 4n, 64x32 warp tile),
// cp.async double-buffered SMEM, padded rows (80B) for conflict-free ldmatrix.
// blockIdx.z selects pointer set.
// ---------------------------------------------------------------------------
constexpr int SM_AH = 0;
constexpr int SM_AL = 10240;
constexpr int SM_BH = 20480;
constexpr int SM_BL = 30720;
constexpr int SM_STAGE = 40960;
constexpr int GEMM_SMEM = 2 * SM_STAGE;   // 80 KB

template<bool GELU, bool WF32, bool WPL>
__global__ void __launch_bounds__(256)
gemm_mma(const __nv_bfloat16* __restrict__ Ah0, const __nv_bfloat16* __restrict__ Al0,
         const __nv_bfloat16* __restrict__ Ah1, const __nv_bfloat16* __restrict__ Al1,
         const __nv_bfloat16* __restrict__ Wh0, const __nv_bfloat16* __restrict__ Wl0,
         const __nv_bfloat16* __restrict__ Wh1, const __nv_bfloat16* __restrict__ Wl1,
         const float* __restrict__ b0, const float* __restrict__ b1,
         float* __restrict__ Cf0, float* __restrict__ Cf1,
         __nv_bfloat16* __restrict__ Ch0, __nv_bfloat16* __restrict__ Cl0,
         __nv_bfloat16* __restrict__ Ch1, __nv_bfloat16* __restrict__ Cl1,
         int N, int K, int lda, int ldc, int ldh) {
    const __nv_bfloat16* Ah = blockIdx.z ? Ah1 : Ah0;
    const __nv_bfloat16* Al = blockIdx.z ? Al1 : Al0;
    const __nv_bfloat16* Wh = blockIdx.z ? Wh1 : Wh0;
    const __nv_bfloat16* Wl = blockIdx.z ? Wl1 : Wl0;
    const float* bias = blockIdx.z ? b1 : b0;
    float*       Cf   = blockIdx.z ? Cf1 : Cf0;
    __nv_bfloat16* Ch = blockIdx.z ? Ch1 : Ch0;
    __nv_bfloat16* Cl = blockIdx.z ? Cl1 : Cl0;

    extern __shared__ char smem[];
    const uint32_t sb = smem_u32(smem);

    const int tid    = threadIdx.x;
    const int lane   = tid & 31;
    const int wid    = tid >> 5;
    const int warp_m = wid >> 2;        // 0..1
    const int warp_n = wid & 3;         // 0..3
    const int bm     = blockIdx.y * 128;
    const int bn     = blockIdx.x * 128;

    // staging mapping: each thread loads 32B (2x16B) per plane per stage
    const int lrow = tid >> 1;          // 0..127
    const int lsegE = (tid & 1) * 16;   // element offset within 32-elem row
    const int lsegB = (tid & 1) * 32;   // byte offset in smem row

    const __nv_bfloat16* gAh = Ah + (size_t)(bm + lrow) * lda + lsegE;
    const __nv_bfloat16* gAl = Al + (size_t)(bm + lrow) * lda + lsegE;
    const __nv_bfloat16* gWh = Wh + (size_t)(bn + lrow) * K   + lsegE;
    const __nv_bfloat16* gWl = Wl + (size_t)(bn + lrow) * K   + lsegE;
    const uint32_t srowA = lrow * 80 + lsegB;

    // ldmatrix base addresses
    const uint32_t aBase = (uint32_t)((warp_m * 64 + (lane & 15)) * 80 +
                                      ((lane >> 4) << 4));
    const uint32_t bBase = (uint32_t)((warp_n * 32 + (lane & 7) +
                                       ((lane & 16) >> 1)) * 80 +
                                      (((lane >> 3) & 1) << 4));

    float d[4][4][4];
    #pragma unroll
    for (int i = 0; i < 4; ++i)
        #pragma unroll
        for (int j = 0; j < 4; ++j)
            #pragma unroll
            for (int k = 0; k < 4; ++k) d[i][j][k] = 0.0f;

    auto load_stage = [&](int s, int kt) {
        const uint32_t sbase = sb + s * SM_STAGE + srowA;
        const int ge = kt * 32;
        CP16(sbase + SM_AH,      gAh + ge);
        CP16(sbase + SM_AH + 16, gAh + ge + 8);
        CP16(sbase + SM_AL,      gAl + ge);
        CP16(sbase + SM_AL + 16, gAl + ge + 8);
        CP16(sbase + SM_BH,      gWh + ge);
        CP16(sbase + SM_BH + 16, gWh + ge + 8);
        CP16(sbase + SM_BL,      gWl + ge);
        CP16(sbase + SM_BL + 16, gWl + ge + 8);
    };

    const int KT = K >> 5;
    load_stage(0, 0); CP_COMMIT();
    load_stage(1, 1); CP_COMMIT();

    for (int kt = 0; kt < KT; ++kt) {
        CP_WAIT1();
        __syncthreads();

        const uint32_t stage = sb + (kt & 1) * SM_STAGE;
        #pragma unroll
        for (int k16 = 0; k16 < 2; ++k16) {
            uint32_t ah[4][4], al[4][4], bh[4][2], bl[4][2];
            #pragma unroll
            for (int mt = 0; mt < 4; ++mt) {
                uint32_t addr = stage + aBase + mt * (16 * 80) + k16 * 32;
                LDSM4(ah[mt][0], ah[mt][1], ah[mt][2], ah[mt][3], addr + SM_AH);
                LDSM4(al[mt][0], al[mt][1], al[mt][2], al[mt][3], addr + SM_AL);
            }
            #pragma unroll
            for (int np = 0; np < 2; ++np) {
                uint32_t addr = stage + bBase + np * (16 * 80) + k16 * 32;
                LDSM4(bh[2*np][0], bh[2*np][1], bh[2*np+1][0], bh[2*np+1][1],
                      addr + SM_BH);
                LDSM4(bl[2*np][0], bl[2*np][1], bl[2*np+1][0], bl[2*np+1][1],
                      addr + SM_BL);
            }
            #pragma unroll
            for (int mt = 0; mt < 4; ++mt)
                #pragma unroll
                for (int nt = 0; nt < 4; ++nt) {
                    MMA_BF16(d[mt][nt], ah[mt], bh[nt]);
                    MMA_BF16(d[mt][nt], ah[mt], bl[nt]);
                    MMA_BF16(d[mt][nt], al[mt], bh[nt]);
                }
        }
        __syncthreads();
        if (kt + 2 < KT) load_stage(kt & 1, kt + 2);
        CP_COMMIT();
    }

    // ------------------------- epilogue -------------------------
    const int grp = lane >> 2;
    const int qd  = lane & 3;
    #pragma unroll
    for (int mt = 0; mt < 4; ++mt) {
        const int r0 = bm + warp_m * 64 + mt * 16 + grp;
        const int r1 = r0 + 8;
        #pragma unroll
        for (int nt = 0; nt < 4; ++nt) {
            const int col = bn + warp_n * 32 + nt * 8 + qd * 2;
            float2 bb = *(const float2*)&bias[col];
            float v00 = d[mt][nt][0] + bb.x;
            float v01 = d[mt][nt][1] + bb.y;
            float v10 = d[mt][nt][2] + bb.x;
            float v11 = d[mt][nt][3] + bb.y;
            if (GELU) {
                v00 = gelu_exact(v00); v01 = gelu_exact(v01);
                v10 = gelu_exact(v10); v11 = gelu_exact(v11);
            }
            if (WF32) {
                *(float2*)&Cf[(size_t)r0 * ldc + col] = make_float2(v00, v01);
                *(float2*)&Cf[(size_t)r1 * ldc + col] = make_float2(v10, v11);
            }
            if (WPL) {
                uint32_t h, l;
                cvt_pair(v00, v01, h, l);
                *(uint32_t*)&Ch[(size_t)r0 * ldh + col] = h;
                *(uint32_t*)&Cl[(size_t)r0 * ldh + col] = l;
                cvt_pair(v10, v11, h, l);
                *(uint32_t*)&Ch[(size_t)r1 * ldh + col] = h;
                *(uint32_t*)&Cl[(size_t)r1 * ldh + col] = l;
            }
        }
    }
}

// ---------------------------------------------------------------------------
// Build Q or K: out[m,0:384]=cc, out[m,384:512]=rope(cr), then GELU(all)
// ---------------------------------------------------------------------------
__global__ void build_qk(const float* __restrict__ cc,
                         const float* __restrict__ qr, int qroff,
                         float* __restrict__ out) {
    int idx = blockIdx.x * blockDim.x + threadIdx.x;
    if (idx >= M * DC) return;
    int m = idx >> 9;
    int c = idx & 511;
    float v;
    if (c < DCC) {
        v = cc[m * DCC + c];
    } else {
        int j = c - DCC;
        int i = j & 63;
        int s = m & (S - 1);
        float invf = expf(-(float)i * (9.2103403719761836f / 64.0f));
        float ang  = (float)s * invf;
        float sv, cv;
        sincosf(ang, &sv, &cv);
        float xj  = qr[m * 256 + qroff + j];
        float rot = (j < 64) ? -qr[m * 256 + qroff + j + 64]
                             :  qr[m * 256 + qroff + j - 64];
        v = xj * cv + rot * sv;
    }
    out[idx] = gelu_exact(v);
}

// ---------------------------------------------------------------------------
// Flash attention (causal). grid = (S/128, H, B), 256 threads.
// Writes O as bf16 hi/lo planes (feeds the OUT GEMM).
// ---------------------------------------------------------------------------
constexpr int ATTN_SMEM_FLOATS = 128*65 + 64*65 + 64*64 + 128*65 + 3*128;
constexpr int ATTN_SMEM_BYTES  = ATTN_SMEM_FLOATS * 4;

__global__ void attn_kernel(const float* __restrict__ Q,
                            const float* __restrict__ K,
                            const float* __restrict__ V,
                            __nv_bfloat16* __restrict__ Oh,
                            __nv_bfloat16* __restrict__ Ol) {
    extern __shared__ float sm[];
    float* Qs   = sm;
    float* Ks   = Qs + 128 * 65;
    float* Vs   = Ks + 64 * 65;
    float* Ps   = Vs + 64 * 64;
    float* mrow = Ps + 128 * 65;
    float* lrow = mrow + 128;
    float* arow = lrow + 128;

    const int qt = blockIdx.x;
    const int h  = blockIdx.y;
    const int b  = blockIdx.z;
    const int q0 = qt * 128;
    const int tid = threadIdx.x;
    const int tx  = tid & 15;
    const int ty  = tid >> 4;
    const float scale = 0.125f;

    const size_t base = (size_t)b * S * DC + h * HD;

    int r8[8];
    #pragma unroll
    for (int i = 0; i < 8; ++i)
        r8[i] = (i < 4) ? (ty * 4 + i) : (64 + ty * 4 + i - 4);

    {
        int r  = tid >> 4;
        int c4 = (tid & 15) * 4;
        for (int rr = r; rr < 128; rr += 16) {
            float4 q4 = *(const float4*)&Q[base + (size_t)(q0 + rr) * DC + c4];
            Qs[rr * 65 + c4 + 0] = q4.x; Qs[rr * 65 + c4 + 1] = q4.y;
            Qs[rr * 65 + c4 + 2] = q4.z; Qs[rr * 65 + c4 + 3] = q4.w;
        }
    }
    if (tid < 128) { mrow[tid] = -INFINITY; lrow[tid] = 0.0f; }

    float acc[8][4];
    #pragma unroll
    for (int i = 0; i < 8; ++i)
        #pragma unroll
        for (int j = 0; j < 4; ++j) acc[i][j] = 0.0f;

    const int kt_end = 2 * qt + 1;
    for (int kt = 0; kt <= kt_end; ++kt) {
        const int k0 = kt * 64;
        const bool do_mask = (k0 + 63 > q0);

        __syncthreads();
        {
            int r  = tid >> 4;
            int c4 = (tid & 15) * 4;
            for (int rr = r; rr < 64; rr += 16) {
                size_t row = base + (size_t)(k0 + rr) * DC + c4;
                float4 k4 = *(const float4*)&K[row];
                float4 v4 = *(const float4*)&V[row];
                Ks[rr * 65 + c4 + 0] = k4.x; Ks[rr * 65 + c4 + 1] = k4.y;
                Ks[rr * 65 + c4 + 2] = k4.z; Ks[rr * 65 + c4 + 3] = k4.w;
                *(float4*)&Vs[rr * 64 + c4] = v4;
            }
        }
        __syncthreads();

        float s_[8][4];
        #pragma unroll
        for (int i = 0; i < 8; ++i)
            #pragma unroll
            for (int j = 0; j < 4; ++j) s_[i][j] = 0.0f;

        #pragma unroll 4
        for (int kk = 0; kk < 64; ++kk) {
            float a[8], w[4];
            #pragma unroll
            for (int i = 0; i < 8; ++i) a[i] = Qs[r8[i] * 65 + kk];
            #pragma unroll
            for (int j = 0; j < 4; ++j) w[j] = Ks[(tx * 4 + j) * 65 + kk];
            #pragma unroll
            for (int i = 0; i < 8; ++i)
                #pragma unroll
                for (int j = 0; j < 4; ++j)
                    s_[i][j] = fmaf(a[i], w[j], s_[i][j]);
        }

        #pragma unroll
        for (int i = 0; i < 8; ++i) {
            int qg = q0 + r8[i];
            #pragma unroll
            for (int j = 0; j < 4; ++j) {
                int kg = k0 + tx * 4 + j;
                float v = s_[i][j] * scale;
                if (do_mask && kg > qg) v = -INFINITY;
                Ps[r8[i] * 65 + tx * 4 + j] = v;
            }
        }
        __syncthreads();

        if (tid < 128) {
            int r = tid;
            float mo = mrow[r];
            float mx = mo;
            #pragma unroll 8
            for (int c = 0; c < 64; ++c) mx = fmaxf(mx, Ps[r * 65 + c]);
            float a = __expf(mo - mx);
            float sum = 0.0f;
            #pragma unroll 8
            for (int c = 0; c < 64; ++c) {
                float p = __expf(Ps[r * 65 + c] - mx);
                Ps[r * 65 + c] = p;
                sum += p;
            }
            mrow[r] = mx;
            lrow[r] = lrow[r] * a + sum;
            arow[r] = a;
        }
        __syncthreads();

        #pragma unroll
        for (int i = 0; i < 8; ++i) {
            float a = arow[r8[i]];
            #pragma unroll
            for (int j = 0; j < 4; ++j) acc[i][j] *= a;
        }
        #pragma unroll 4
        for (int kk = 0; kk < 64; ++kk) {
            float p[8];
            #pragma unroll
            for (int i = 0; i < 8; ++i) p[i] = Ps[r8[i] * 65 + kk];
            float4 v4 = *(const float4*)&Vs[kk * 64 + tx * 4];
            float w[4] = {v4.x, v4.y, v4.z, v4.w};
            #pragma unroll
            for (int i = 0; i < 8; ++i)
                #pragma unroll
                for (int j = 0; j < 4; ++j)
                    acc[i][j] = fmaf(p[i], w[j], acc[i][j]);
        }
    }

    __syncthreads();
    #pragma unroll
    for (int i = 0; i < 8; ++i) {
        float inv = 1.0f / lrow[r8[i]];
        float o0 = acc[i][0] * inv, o1 = acc[i][1] * inv;
        float o2 = acc[i][2] * inv, o3 = acc[i][3] * inv;
        uint32_t h0, l0, h1, l1;
        cvt_pair(o0, o1, h0, l0);
        cvt_pair(o2, o3, h1, l1);
        size_t idx = base + (size_t)(q0 + r8[i]) * DC + tx * 4;
        *(uint2*)&Oh[idx] = make_uint2(h0, h1);
        *(uint2*)&Ol[idx] = make_uint2(l0, l1);
    }
}

// ---------------------------------------------------------------------------
// Launch
// ---------------------------------------------------------------------------
extern "C" void kernel_launch(void* const* d_in, const int* in_sizes, int n_in,
                              void* d_out, int out_size) {
    const float* x     = (const float*)d_in[0];
    const float* CQ_w  = (const float*)d_in[1];
    const float* CQ_b  = (const float*)d_in[2];
    const float* CQC_w = (const float*)d_in[3];
    const float* CQC_b = (const float*)d_in[4];
    const float* CQR_w = (const float*)d_in[5];
    const float* CQR_b = (const float*)d_in[6];
    const float* CKV_w = (const float*)d_in[7];
    const float* CKV_b = (const float*)d_in[8];
    const float* CKR_w = (const float*)d_in[9];
    const float* CKR_b = (const float*)d_in[10];
    const float* CKC_w = (const float*)d_in[11];
    const float* CKC_b = (const float*)d_in[12];
    const float* CV_w  = (const float*)d_in[13];
    const float* CV_b  = (const float*)d_in[14];
    const float* OUT_w = (const float*)d_in[15];
    const float* OUT_b = (const float*)d_in[16];
    float* out = (float*)d_out;

    __nv_bfloat16 *xh, *xl, *wh, *wl, *cqkvh, *cqkvl, *oh, *ol;
    float *qr, *cc, *Qb, *Kb, *Vb;
    cudaGetSymbolAddress((void**)&xh,    g_xh);
    cudaGetSymbolAddress((void**)&xl,    g_xl);
    cudaGetSymbolAddress((void**)&wh,    g_wh);
    cudaGetSymbolAddress((void**)&wl,    g_wl);
    cudaGetSymbolAddress((void**)&cqkvh, g_cqkvh);
    cudaGetSymbolAddress((void**)&cqkvl, g_cqkvl);
    cudaGetSymbolAddress((void**)&oh,    g_oh);
    cudaGetSymbolAddress((void**)&ol,    g_ol);
    cudaGetSymbolAddress((void**)&qr,    g_qr);
    cudaGetSymbolAddress((void**)&cc,    g_cc);
    cudaGetSymbolAddress((void**)&Qb,    g_Q);
    cudaGetSymbolAddress((void**)&Kb,    g_K);
    cudaGetSymbolAddress((void**)&Vb,    g_V);

    cudaFuncSetAttribute(gemm_mma<true , false, true >,
                         cudaFuncAttributeMaxDynamicSharedMemorySize, GEMM_SMEM);
    cudaFuncSetAttribute(gemm_mma<false, true , false>,
                         cudaFuncAttributeMaxDynamicSharedMemorySize, GEMM_SMEM);
    cudaFuncSetAttribute(attn_kernel,
                         cudaFuncAttributeMaxDynamicSharedMemorySize, ATTN_SMEM_BYTES);

    // ---- bf16 hi/lo plane conversion (x + all weights) ----
    auto cvt = [&](const float* src, __nv_bfloat16* h, __nv_bfloat16* l, size_t n) {
        int n4 = (int)(n / 4);
        cvt_planes<<<(n4 + 255) / 256, 256>>>(src, h, l, n4);
    };
    cvt(x,     xh,           xl,           (size_t)M * 2048);
    cvt(CQ_w,  wh + OFF_Q,   wl + OFF_Q,   512 * 2048);
    cvt(CKV_w, wh + OFF_KV,  wl + OFF_KV,  512 * 2048);
    cvt(CQR_w, wh + OFF_QR,  wl + OFF_QR,  128 * 2048);
    cvt(CKR_w, wh + OFF_KR,  wl + OFF_KR,  128 * 2048);
    cvt(CQC_w, wh + OFF_QC,  wl + OFF_QC,  384 * 512);
    cvt(CKC_w, wh + OFF_KC,  wl + OFF_KC,  384 * 512);
    cvt(CV_w,  wh + OFF_V,   wl + OFF_V,   512 * 512);
    cvt(OUT_w, wh + OFF_OUT, wl + OFF_OUT, 2048 * 512);

    dim3 blk(256);
    const int GY = M / 128;   // 64

    // (1) z=0: cq planes = gelu(x@CQ^T+b); z=1: ckv planes  [M,512] each
    gemm_mma<true , false, true ><<<dim3(4, GY, 2), blk, GEMM_SMEM>>>(
        xh, xl, xh, xl,
        wh + OFF_Q, wl + OFF_Q, wh + OFF_KV, wl + OFF_KV,
        CQ_b, CKV_b,
        nullptr, nullptr,
        cqkvh, cqkvl, cqkvh + 512, cqkvl + 512,
        512, EMBED, EMBED, 0, 1024);

    // (2) z=0: cqr; z=1: ckr  (fp32)  [M,128] each
    gemm_mma<false, true , false><<<dim3(1, GY, 2), blk, GEMM_SMEM>>>(
        xh, xl, xh, xl,
        wh + OFF_QR, wl + OFF_QR, wh + OFF_KR, wl + OFF_KR,
        CQR_b, CKR_b,
        qr, qr + 128,
        nullptr, nullptr, nullptr, nullptr,
        128, EMBED, EMBED, 256, 0);

    // (3) z=0: cqc = cq@CQC^T; z=1: ckc = ckv@CKC^T  (fp32)  [M,384] each
    gemm_mma<false, true , false><<<dim3(3, GY, 2), blk, GEMM_SMEM>>>(
        cqkvh, cqkvl, cqkvh + 512, cqkvl + 512,
        wh + OFF_QC, wl + OFF_QC, wh + OFF_KC, wl + OFF_KC,
        CQC_b, CKC_b,
        cc, cc + (size_t)M * DCC,
        nullptr, nullptr, nullptr, nullptr,
        DCC, DC, 1024, DCC, 0);

    // (4) V = ckv @ CV^T + b  (fp32)  [M,512]
    gemm_mma<false, true , false><<<dim3(4, GY, 1), blk, GEMM_SMEM>>>(
        cqkvh + 512, cqkvl + 512, cqkvh + 512, cqkvl + 512,
        wh + OFF_V, wl + OFF_V, wh + OFF_V, wl + OFF_V,
        CV_b, CV_b,
        Vb, Vb,
        nullptr, nullptr, nullptr, nullptr,
        DC, DC, 1024, DC, 0);

    // Q/K build (concat + rope + gelu)
    int nelem = M * DC;
    int nblk  = (nelem + 255) / 256;
    build_qk<<<nblk, 256>>>(cc, qr, 0, Qb);
    build_qk<<<nblk, 256>>>(cc + (size_t)M * DCC, qr, 128, Kb);

    // causal flash attention -> O planes
    attn_kernel<<<dim3(S/128, H, B), blk, ATTN_SMEM_BYTES>>>(Qb, Kb, Vb, oh, ol);

    // (5) out = O @ OUT^T + b  (fp32)  [M,2048]
    gemm_mma<false, true , false><<<dim3(16, GY, 1), blk, GEMM_SMEM>>>(
        oh, ol, oh, ol,
        wh + OFF_OUT, wl + OFF_OUT, wh + OFF_OUT, wl + OFF_OUT,
        OUT_b, OUT_b,
        out, out,
        nullptr, nullptr, nullptr, nullptr,
        EMBED, DC, DC, EMBED, 0);
}

// round 5
// speedup vs baseline: 6.1691x; 1.4796x over previous
#include <cuda_runtime.h>
#include <cuda_bf16.h>
#include <math.h>
#include <stdint.h>

// ---------------------------------------------------------------------------
// Problem constants
// ---------------------------------------------------------------------------
constexpr int B     = 4;
constexpr int S     = 2048;
constexpr int EMBED = 2048;
constexpr int DC    = 512;     // D_COMPR
constexpr int DR    = 128;     // D_ROPE
constexpr int DCC   = DC - DR; // 384
constexpr int H     = 8;
constexpr int HD    = 64;      // head dim
constexpr int M     = B * S;   // 8192 rows

// weight-plane offsets (elements) inside g_wh / g_wl
constexpr size_t OFF_Q   = 0;
constexpr size_t OFF_KV  = OFF_Q   + 512 * 2048;
constexpr size_t OFF_QR  = OFF_KV  + 512 * 2048;
constexpr size_t OFF_KR  = OFF_QR  + 128 * 2048;
constexpr size_t OFF_QC  = OFF_KR  + 128 * 2048;
constexpr size_t OFF_KC  = OFF_QC  + 384 * 512;
constexpr size_t OFF_V   = OFF_KC  + 384 * 512;
constexpr size_t OFF_OUT = OFF_V   + 512 * 512;
constexpr size_t W_TOTAL = OFF_OUT + 2048 * 512;

// ---------------------------------------------------------------------------
// Scratch (device globals; allocation is forbidden)
// ---------------------------------------------------------------------------
__device__ __align__(16) __nv_bfloat16 g_xh[(size_t)M * 2048];
__device__ __align__(16) __nv_bfloat16 g_xl[(size_t)M * 2048];
__device__ __align__(16) __nv_bfloat16 g_wh[W_TOTAL];
__device__ __align__(16) __nv_bfloat16 g_wl[W_TOTAL];
__device__ __align__(16) __nv_bfloat16 g_cqkvh[(size_t)M * 1024];
__device__ __align__(16) __nv_bfloat16 g_cqkvl[(size_t)M * 1024];
__device__ __align__(16) __nv_bfloat16 g_qh[(size_t)M * 512];
__device__ __align__(16) __nv_bfloat16 g_ql[(size_t)M * 512];
__device__ __align__(16) __nv_bfloat16 g_kh[(size_t)M * 512];
__device__ __align__(16) __nv_bfloat16 g_kl[(size_t)M * 512];
__device__ __align__(16) __nv_bfloat16 g_vh[(size_t)M * 512];
__device__ __align__(16) __nv_bfloat16 g_vl[(size_t)M * 512];
__device__ __align__(16) __nv_bfloat16 g_oh[(size_t)M * 512];
__device__ __align__(16) __nv_bfloat16 g_ol[(size_t)M * 512];
__device__ float g_qr [M * 256];       // cols 0-127: cqr, 128-255: ckr
__device__ float g_cc [2 * M * DCC];   // [0]: cqc, [1]: ckc

__device__ __forceinline__ float gelu_exact(float v) {
    return 0.5f * v * (1.0f + erff(v * 0.70710678118654752f));
}

// fp32 pair -> bf16x2 hi + bf16x2 lo residual
__device__ __forceinline__ void cvt_pair(float e0, float e1,
                                         uint32_t& h, uint32_t& l) {
    asm("cvt.rn.bf16x2.f32 %0, %1, %2;" : "=r"(h) : "f"(e1), "f"(e0));
    float h0 = __uint_as_float(h << 16);
    float h1 = __uint_as_float(h & 0xFFFF0000u);
    asm("cvt.rn.bf16x2.f32 %0, %1, %2;" : "=r"(l) : "f"(e1 - h1), "f"(e0 - h0));
}

// FMA-pipe exp (no MUFU): exp(x) for x <= 0, clamped at -80.
__device__ __forceinline__ float fast_exp(float x) {
    x = fmaxf(x, -80.0f);
    float t = fmaf(x, 1.4426950408889634f, 12582912.0f);
    float i = t - 12582912.0f;
    float f = fmaf(x, 1.4426950408889634f, -i);
    float p = 1.3333558146e-3f;
    p = fmaf(p, f, 9.6181291076e-3f);
    p = fmaf(p, f, 5.5504108665e-2f);
    p = fmaf(p, f, 2.4022650696e-1f);
    p = fmaf(p, f, 6.9314718056e-1f);
    p = fmaf(p, f, 1.0f);
    return __int_as_float(__float_as_int(p) +
                          ((__float_as_int(t) - 0x4B400000) << 23));
}

__device__ __forceinline__ uint32_t smem_u32(const void* p) {
    uint32_t a;
    asm("{ .reg .u64 t; cvta.to.shared.u64 t, %1; cvt.u32.u64 %0, t; }"
        : "=r"(a) : "l"(p));
    return a;
}

#define CP16(dst, src) \
    asm volatile("cp.async.cg.shared.global [%0], [%1], 16;" \
                 :: "r"(dst), "l"(src) : "memory")
#define CP_COMMIT() asm volatile("cp.async.commit_group;" ::: "memory")
#define CP_WAIT1()  asm volatile("cp.async.wait_group 1;" ::: "memory")
#define CP_WAIT0()  asm volatile("cp.async.wait_group 0;" ::: "memory")

#define LDSM4(r0, r1, r2, r3, addr) \
    asm volatile("ldmatrix.sync.aligned.m8n8.x4.shared.b16 {%0,%1,%2,%3}, [%4];" \
                 : "=r"(r0), "=r"(r1), "=r"(r2), "=r"(r3) : "r"(addr))
#define LDSM4T(r0, r1, r2, r3, addr) \
    asm volatile("ldmatrix.sync.aligned.m8n8.x4.trans.shared.b16 {%0,%1,%2,%3}, [%4];" \
                 : "=r"(r0), "=r"(r1), "=r"(r2), "=r"(r3) : "r"(addr))

#define MMA_BF16(d, a, b) \
    asm volatile("mma.sync.aligned.m16n8k16.row.col.f32.bf16.bf16.f32 " \
                 "{%0,%1,%2,%3},{%4,%5,%6,%7},{%8,%9},{%0,%1,%2,%3};" \
                 : "+f"((d)[0]), "+f"((d)[1]), "+f"((d)[2]), "+f"((d)[3]) \
                 : "r"((a)[0]), "r"((a)[1]), "r"((a)[2]), "r"((a)[3]), \
                   "r"((b)[0]), "r"((b)[1]))

// ---------------------------------------------------------------------------
// fp32 -> bf16 hi/lo planes
// ---------------------------------------------------------------------------
__global__ void cvt_planes(const float* __restrict__ src,
                           __nv_bfloat16* __restrict__ h,
                           __nv_bfloat16* __restrict__ l, int n4) {
    int i = blockIdx.x * blockDim.x + threadIdx.x;
    if (i >= n4) return;
    float4 v = ((const float4*)src)[i];
    uint32_t h0, h1, l0, l1;
    cvt_pair(v.x, v.y, h0, l0);
    cvt_pair(v.z, v.w, h1, l1);
    ((uint2*)h)[i] = make_uint2(h0, h1);
    ((uint2*)l)[i] = make_uint2(l0, l1);
}

// ---------------------------------------------------------------------------
// Tensor-core GEMM via mma.sync (bf16 hi/lo split, fp32 accumulate)
// ---------------------------------------------------------------------------
constexpr int SM_AH = 0;
constexpr int SM_AL = 10240;
constexpr int SM_BH = 20480;
constexpr int SM_BL = 30720;
constexpr int SM_STAGE = 40960;
constexpr int GEMM_SMEM = 2 * SM_STAGE;

template<bool GELU, bool WF32, bool WPL>
__global__ void __launch_bounds__(256)
gemm_mma(const __nv_bfloat16* __restrict__ Ah0, const __nv_bfloat16* __restrict__ Al0,
         const __nv_bfloat16* __restrict__ Ah1, const __nv_bfloat16* __restrict__ Al1,
         const __nv_bfloat16* __restrict__ Wh0, const __nv_bfloat16* __restrict__ Wl0,
         const __nv_bfloat16* __restrict__ Wh1, const __nv_bfloat16* __restrict__ Wl1,
         const float* __restrict__ b0, const float* __restrict__ b1,
         float* __restrict__ Cf0, float* __restrict__ Cf1,
         __nv_bfloat16* __restrict__ Ch0, __nv_bfloat16* __restrict__ Cl0,
         __nv_bfloat16* __restrict__ Ch1, __nv_bfloat16* __restrict__ Cl1,
         int N, int K, int lda, int ldc, int ldh) {
    const __nv_bfloat16* Ah = blockIdx.z ? Ah1 : Ah0;
    const __nv_bfloat16* Al = blockIdx.z ? Al1 : Al0;
    const __nv_bfloat16* Wh = blockIdx.z ? Wh1 : Wh0;
    const __nv_bfloat16* Wl = blockIdx.z ? Wl1 : Wl0;
    const float* bias = blockIdx.z ? b1 : b0;
    float*       Cf   = blockIdx.z ? Cf1 : Cf0;
    __nv_bfloat16* Ch = blockIdx.z ? Ch1 : Ch0;
    __nv_bfloat16* Cl = blockIdx.z ? Cl1 : Cl0;

    extern __shared__ char smem[];
    const uint32_t sb = smem_u32(smem);

    const int tid    = threadIdx.x;
    const int lane   = tid & 31;
    const int wid    = tid >> 5;
    const int warp_m = wid >> 2;
    const int warp_n = wid & 3;
    const int bm     = blockIdx.y * 128;
    const int bn     = blockIdx.x * 128;

    const int lrow = tid >> 1;
    const int lsegE = (tid & 1) * 16;
    const int lsegB = (tid & 1) * 32;

    const __nv_bfloat16* gAh = Ah + (size_t)(bm + lrow) * lda + lsegE;
    const __nv_bfloat16* gAl = Al + (size_t)(bm + lrow) * lda + lsegE;
    const __nv_bfloat16* gWh = Wh + (size_t)(bn + lrow) * K   + lsegE;
    const __nv_bfloat16* gWl = Wl + (size_t)(bn + lrow) * K   + lsegE;
    const uint32_t srowA = lrow * 80 + lsegB;

    const uint32_t aBase = (uint32_t)((warp_m * 64 + (lane & 15)) * 80 +
                                      ((lane >> 4) << 4));
    const uint32_t bBase = (uint32_t)((warp_n * 32 + (lane & 7) +
                                       ((lane & 16) >> 1)) * 80 +
                                      (((lane >> 3) & 1) << 4));

    float d[4][4][4];
    #pragma unroll
    for (int i = 0; i < 4; ++i)
        #pragma unroll
        for (int j = 0; j < 4; ++j)
            #pragma unroll
            for (int k = 0; k < 4; ++k) d[i][j][k] = 0.0f;

    auto load_stage = [&](int s, int kt) {
        const uint32_t sbase = sb + s * SM_STAGE + srowA;
        const int ge = kt * 32;
        CP16(sbase + SM_AH,      gAh + ge);
        CP16(sbase + SM_AH + 16, gAh + ge + 8);
        CP16(sbase + SM_AL,      gAl + ge);
        CP16(sbase + SM_AL + 16, gAl + ge + 8);
        CP16(sbase + SM_BH,      gWh + ge);
        CP16(sbase + SM_BH + 16, gWh + ge + 8);
        CP16(sbase + SM_BL,      gWl + ge);
        CP16(sbase + SM_BL + 16, gWl + ge + 8);
    };

    const int KT = K >> 5;
    load_stage(0, 0); CP_COMMIT();
    load_stage(1, 1); CP_COMMIT();

    for (int kt = 0; kt < KT; ++kt) {
        CP_WAIT1();
        __syncthreads();

        const uint32_t stage = sb + (kt & 1) * SM_STAGE;
        #pragma unroll
        for (int k16 = 0; k16 < 2; ++k16) {
            uint32_t ah[4][4], al[4][4], bh[4][2], bl[4][2];
            #pragma unroll
            for (int mt = 0; mt < 4; ++mt) {
                uint32_t addr = stage + aBase + mt * (16 * 80) + k16 * 32;
                LDSM4(ah[mt][0], ah[mt][1], ah[mt][2], ah[mt][3], addr + SM_AH);
                LDSM4(al[mt][0], al[mt][1], al[mt][2], al[mt][3], addr + SM_AL);
            }
            #pragma unroll
            for (int np = 0; np < 2; ++np) {
                uint32_t addr = stage + bBase + np * (16 * 80) + k16 * 32;
                LDSM4(bh[2*np][0], bh[2*np][1], bh[2*np+1][0], bh[2*np+1][1],
                      addr + SM_BH);
                LDSM4(bl[2*np][0], bl[2*np][1], bl[2*np+1][0], bl[2*np+1][1],
                      addr + SM_BL);
            }
            #pragma unroll
            for (int mt = 0; mt < 4; ++mt)
                #pragma unroll
                for (int nt = 0; nt < 4; ++nt) {
                    MMA_BF16(d[mt][nt], ah[mt], bh[nt]);
                    MMA_BF16(d[mt][nt], ah[mt], bl[nt]);
                    MMA_BF16(d[mt][nt], al[mt], bh[nt]);
                }
        }
        __syncthreads();
        if (kt + 2 < KT) load_stage(kt & 1, kt + 2);
        CP_COMMIT();
    }

    const int grp = lane >> 2;
    const int qd  = lane & 3;
    #pragma unroll
    for (int mt = 0; mt < 4; ++mt) {
        const int r0 = bm + warp_m * 64 + mt * 16 + grp;
        const int r1 = r0 + 8;
        #pragma unroll
        for (int nt = 0; nt < 4; ++nt) {
            const int col = bn + warp_n * 32 + nt * 8 + qd * 2;
            float2 bb = *(const float2*)&bias[col];
            float v00 = d[mt][nt][0] + bb.x;
            float v01 = d[mt][nt][1] + bb.y;
            float v10 = d[mt][nt][2] + bb.x;
            float v11 = d[mt][nt][3] + bb.y;
            if (GELU) {
                v00 = gelu_exact(v00); v01 = gelu_exact(v01);
                v10 = gelu_exact(v10); v11 = gelu_exact(v11);
            }
            if (WF32) {
                *(float2*)&Cf[(size_t)r0 * ldc + col] = make_float2(v00, v01);
                *(float2*)&Cf[(size_t)r1 * ldc + col] = make_float2(v10, v11);
            }
            if (WPL) {
                uint32_t h, l;
                cvt_pair(v00, v01, h, l);
                *(uint32_t*)&Ch[(size_t)r0 * ldh + col] = h;
                *(uint32_t*)&Cl[(size_t)r0 * ldh + col] = l;
                cvt_pair(v10, v11, h, l);
                *(uint32_t*)&Ch[(size_t)r1 * ldh + col] = h;
                *(uint32_t*)&Cl[(size_t)r1 * ldh + col] = l;
            }
        }
    }
}

// ---------------------------------------------------------------------------
// Build Q or K as bf16 hi/lo planes: concat + rope + gelu (+ score scale)
// ---------------------------------------------------------------------------
__global__ void build_qk_planes(const float* __restrict__ cc,
                                const float* __restrict__ qr, int qroff,
                                __nv_bfloat16* __restrict__ oh,
                                __nv_bfloat16* __restrict__ ol,
                                float scale) {
    int idx = blockIdx.x * blockDim.x + threadIdx.x;   // pair index
    if (idx >= M * 256) return;
    int m = idx >> 8;
    int cp = idx & 255;
    int c = cp * 2;
    float v0, v1;
    if (c < DCC) {
        float2 t = *(const float2*)&cc[(size_t)m * DCC + c];
        v0 = t.x; v1 = t.y;
    } else {
        int j = c - DCC;
        int s = m & (S - 1);
        float vv[2];
        #pragma unroll
        for (int e = 0; e < 2; ++e) {
            int jj = j + e;
            int i = jj & 63;
            float invf = expf(-(float)i * (9.2103403719761836f / 64.0f));
            float ang  = (float)s * invf;
            float sv, cv; sincosf(ang, &sv, &cv);
            float xj  = qr[m * 256 + qroff + jj];
            float rot = (jj < 64) ? -qr[m * 256 + qroff + jj + 64]
                                  :  qr[m * 256 + qroff + jj - 64];
            vv[e] = xj * cv + rot * sv;
        }
        v0 = vv[0]; v1 = vv[1];
    }
    v0 = gelu_exact(v0) * scale;
    v1 = gelu_exact(v1) * scale;
    uint32_t h, l;
    cvt_pair(v0, v1, h, l);
    *(uint32_t*)&oh[(size_t)m * DC + c] = h;
    *(uint32_t*)&ol[(size_t)m * DC + c] = l;
}

// ---------------------------------------------------------------------------
// Flash attention via mma.sync, register-resident softmax.
// grid = (S/128, H, B), 256 threads (8 warps x 16 query rows each).
// Q pre-scaled by 1/8. K tile = 64 keys/iter, cp.async double-buffered.
// ---------------------------------------------------------------------------
constexpr int AT_QH   = 0;
constexpr int AT_QL   = 18432;             // 128*144
constexpr int AT_ST0  = 36864;
constexpr int AT_KH   = 0;                 // within stage
constexpr int AT_KL   = 9216;              // 64*144
constexpr int AT_VH   = 18432;
constexpr int AT_VL   = 27648;
constexpr int AT_STSZ = 36864;
constexpr int ATTN_SMEM = AT_ST0 + 2 * AT_STSZ;   // 110592

__global__ void __launch_bounds__(256)
attn_mma(const __nv_bfloat16* __restrict__ Qh, const __nv_bfloat16* __restrict__ Ql,
         const __nv_bfloat16* __restrict__ Kh, const __nv_bfloat16* __restrict__ Kl,
         const __nv_bfloat16* __restrict__ Vh, const __nv_bfloat16* __restrict__ Vl,
         __nv_bfloat16* __restrict__ Oh, __nv_bfloat16* __restrict__ Ol) {
    extern __shared__ char smem[];
    const uint32_t sb = smem_u32(smem);

    const int qt = blockIdx.x, h = blockIdx.y, b = blockIdx.z;
    const int q0 = qt * 128;
    const int tid  = threadIdx.x;
    const int lane = tid & 31;
    const int wid  = tid >> 5;
    const int m0   = wid * 16;
    const int grp  = lane >> 2;
    const int qd   = lane & 3;
    const int bS   = b * S;
    const size_t hoff = (size_t)h * HD;

    // ---- load Q tile (both planes) ----
    {
        int r  = tid >> 1;              // 0..127
        int ch = (tid & 1) * 4;         // chunk pairs
        size_t g = (size_t)(bS + q0 + r) * DC + hoff + ch * 8;
        uint32_t sdst = sb + AT_QH + r * 144 + ch * 16;
        #pragma unroll
        for (int c = 0; c < 4; ++c) {
            CP16(sdst + c * 16,             Qh + g + c * 8);
            CP16(sdst + 18432 + c * 16,     Ql + g + c * 8);
        }
    }
    // prefetch K/V tile 0
    auto load_kv = [&](int kt, int buf) {
        const uint32_t stage = sb + AT_ST0 + buf * AT_STSZ;
        int r  = tid >> 2;              // 0..63
        int ch = (tid & 3) * 2;         // 2 chunks
        size_t g = (size_t)(bS + kt * 64 + r) * DC + hoff + ch * 8;
        uint32_t sdst = stage + r * 144 + ch * 16;
        #pragma unroll
        for (int c = 0; c < 2; ++c) {
            CP16(sdst + AT_KH + c * 16, Kh + g + c * 8);
            CP16(sdst + AT_KL + c * 16, Kl + g + c * 8);
            CP16(sdst + AT_VH + c * 16, Vh + g + c * 8);
            CP16(sdst + AT_VL + c * 16, Vl + g + c * 8);
        }
    };
    load_kv(0, 0);
    CP_COMMIT();

    float mrow[2] = {-1e30f, -1e30f};
    float lrow[2] = {0.0f, 0.0f};
    float acc[8][4];
    #pragma unroll
    for (int j = 0; j < 8; ++j)
        #pragma unroll
        for (int c = 0; c < 4; ++c) acc[j][c] = 0.0f;

    const uint32_t aBase = sb + AT_QH + (m0 + (lane & 15)) * 144 +
                           ((lane >> 4) << 4);
    const uint32_t bRow  = ((lane & 7) + ((lane & 16) >> 1)) * 144 +
                           (((lane >> 3) & 1) << 4);
    const uint32_t vRow  = (lane & 15) * 144 + ((lane >> 4) << 4);

    const int kt_end = 2 * qt + 1;
    for (int kt = 0; kt <= kt_end; ++kt) {
        CP_WAIT0();
        __syncthreads();
        if (kt < kt_end) { load_kv(kt + 1, (kt + 1) & 1); }
        CP_COMMIT();

        const uint32_t stage = sb + AT_ST0 + (kt & 1) * AT_STSZ;
        const int k0 = kt * 64;

        // ---- scores: s = Q @ K^T (pre-scaled), hi/lo 3-term ----
        float s[8][4];
        #pragma unroll
        for (int j = 0; j < 8; ++j)
            #pragma unroll
            for (int c = 0; c < 4; ++c) s[j][c] = 0.0f;

        #pragma unroll
        for (int k16 = 0; k16 < 4; ++k16) {
            uint32_t qh[4], ql[4];
            LDSM4(qh[0], qh[1], qh[2], qh[3], aBase + k16 * 32);
            LDSM4(ql[0], ql[1], ql[2], ql[3], aBase + 18432 + k16 * 32);
            #pragma unroll
            for (int np = 0; np < 4; ++np) {
                uint32_t kh[4], kl[4];
                uint32_t baddr = stage + bRow + np * (16 * 144) + k16 * 32;
                LDSM4(kh[0], kh[1], kh[2], kh[3], baddr + AT_KH);
                LDSM4(kl[0], kl[1], kl[2], kl[3], baddr + AT_KL);
                MMA_BF16(s[2*np],   qh, kh);
                MMA_BF16(s[2*np],   qh, kl);
                MMA_BF16(s[2*np],   ql, kh);
                MMA_BF16(s[2*np+1], qh, kh + 2);
                MMA_BF16(s[2*np+1], qh, kl + 2);
                MMA_BF16(s[2*np+1], ql, kh + 2);
            }
        }

        // ---- causal mask ----
        const int row0 = q0 + m0 + grp;
        if (k0 + 63 > q0 + m0) {
            #pragma unroll
            for (int j = 0; j < 8; ++j) {
                int kg = k0 + j * 8 + qd * 2;
                if (kg     > row0)     s[j][0] = -1e30f;
                if (kg + 1 > row0)     s[j][1] = -1e30f;
                if (kg     > row0 + 8) s[j][2] = -1e30f;
                if (kg + 1 > row0 + 8) s[j][3] = -1e30f;
            }
        }

        // ---- online softmax (registers + quad shuffles) ----
        float mx0 = -1e30f, mx1 = -1e30f;
        #pragma unroll
        for (int j = 0; j < 8; ++j) {
            mx0 = fmaxf(mx0, fmaxf(s[j][0], s[j][1]));
            mx1 = fmaxf(mx1, fmaxf(s[j][2], s[j][3]));
        }
        mx0 = fmaxf(mx0, __shfl_xor_sync(0xFFFFFFFF, mx0, 1));
        mx0 = fmaxf(mx0, __shfl_xor_sync(0xFFFFFFFF, mx0, 2));
        mx1 = fmaxf(mx1, __shfl_xor_sync(0xFFFFFFFF, mx1, 1));
        mx1 = fmaxf(mx1, __shfl_xor_sync(0xFFFFFFFF, mx1, 2));
        float mn0 = fmaxf(mrow[0], mx0);
        float mn1 = fmaxf(mrow[1], mx1);
        float al0 = fast_exp(mrow[0] - mn0);
        float al1 = fast_exp(mrow[1] - mn1);
        mrow[0] = mn0; mrow[1] = mn1;

        float sum0 = 0.0f, sum1 = 0.0f;
        #pragma unroll
        for (int j = 0; j < 8; ++j) {
            s[j][0] = fast_exp(s[j][0] - mn0); sum0 += s[j][0];
            s[j][1] = fast_exp(s[j][1] - mn0); sum0 += s[j][1];
            s[j][2] = fast_exp(s[j][2] - mn1); sum1 += s[j][2];
            s[j][3] = fast_exp(s[j][3] - mn1); sum1 += s[j][3];
        }
        sum0 += __shfl_xor_sync(0xFFFFFFFF, sum0, 1);
        sum0 += __shfl_xor_sync(0xFFFFFFFF, sum0, 2);
        sum1 += __shfl_xor_sync(0xFFFFFFFF, sum1, 1);
        sum1 += __shfl_xor_sync(0xFFFFFFFF, sum1, 2);
        lrow[0] = lrow[0] * al0 + sum0;
        lrow[1] = lrow[1] * al1 + sum1;

        #pragma unroll
        for (int j = 0; j < 8; ++j) {
            acc[j][0] *= al0; acc[j][1] *= al0;
            acc[j][2] *= al1; acc[j][3] *= al1;
        }

        // ---- acc += P @ V (hi/lo 3-term, V via ldmatrix.trans) ----
        #pragma unroll
        for (int k2 = 0; k2 < 4; ++k2) {
            uint32_t pah[4], pal[4];
            cvt_pair(s[2*k2][0],   s[2*k2][1],   pah[0], pal[0]);
            cvt_pair(s[2*k2][2],   s[2*k2][3],   pah[1], pal[1]);
            cvt_pair(s[2*k2+1][0], s[2*k2+1][1], pah[2], pal[2]);
            cvt_pair(s[2*k2+1][2], s[2*k2+1][3], pah[3], pal[3]);
            #pragma unroll
            for (int np = 0; np < 4; ++np) {
                uint32_t vh[4], vl[4];
                uint32_t vaddr = stage + vRow + k2 * (16 * 144) + np * 32;
                LDSM4T(vh[0], vh[1], vh[2], vh[3], vaddr + AT_VH);
                LDSM4T(vl[0], vl[1], vl[2], vl[3], vaddr + AT_VL);
                MMA_BF16(acc[2*np],   pah, vh);
                MMA_BF16(acc[2*np],   pah, vl);
                MMA_BF16(acc[2*np],   pal, vh);
                MMA_BF16(acc[2*np+1], pah, vh + 2);
                MMA_BF16(acc[2*np+1], pah, vl + 2);
                MMA_BF16(acc[2*np+1], pal, vh + 2);
            }
        }
    }

    // ---- epilogue: O planes ----
    const float inv0 = 1.0f / lrow[0];
    const float inv1 = 1.0f / lrow[1];
    const int row0 = q0 + m0 + grp;
    const size_t ob0 = (size_t)(bS + row0) * DC + hoff;
    const size_t ob1 = (size_t)(bS + row0 + 8) * DC + hoff;
    #pragma unroll
    for (int j = 0; j < 8; ++j) {
        int col = j * 8 + qd * 2;
        uint32_t hh, ll;
        cvt_pair(acc[j][0] * inv0, acc[j][1] * inv0, hh, ll);
        *(uint32_t*)&Oh[ob0 + col] = hh;
        *(uint32_t*)&Ol[ob0 + col] = ll;
        cvt_pair(acc[j][2] * inv1, acc[j][3] * inv1, hh, ll);
        *(uint32_t*)&Oh[ob1 + col] = hh;
        *(uint32_t*)&Ol[ob1 + col] = ll;
    }
}

// ---------------------------------------------------------------------------
// Launch
// ---------------------------------------------------------------------------
extern "C" void kernel_launch(void* const* d_in, const int* in_sizes, int n_in,
                              void* d_out, int out_size) {
    const float* x     = (const float*)d_in[0];
    const float* CQ_w  = (const float*)d_in[1];
    const float* CQ_b  = (const float*)d_in[2];
    const float* CQC_w = (const float*)d_in[3];
    const float* CQC_b = (const float*)d_in[4];
    const float* CQR_w = (const float*)d_in[5];
    const float* CQR_b = (const float*)d_in[6];
    const float* CKV_w = (const float*)d_in[7];
    const float* CKV_b = (const float*)d_in[8];
    const float* CKR_w = (const float*)d_in[9];
    const float* CKR_b = (const float*)d_in[10];
    const float* CKC_w = (const float*)d_in[11];
    const float* CKC_b = (const float*)d_in[12];
    const float* CV_w  = (const float*)d_in[13];
    const float* CV_b  = (const float*)d_in[14];
    const float* OUT_w = (const float*)d_in[15];
    const float* OUT_b = (const float*)d_in[16];
    float* out = (float*)d_out;

    __nv_bfloat16 *xh, *xl, *wh, *wl, *cqkvh, *cqkvl;
    __nv_bfloat16 *qh, *ql, *kh, *kl, *vh, *vl, *oh, *ol;
    float *qr, *cc;
    cudaGetSymbolAddress((void**)&xh,    g_xh);
    cudaGetSymbolAddress((void**)&xl,    g_xl);
    cudaGetSymbolAddress((void**)&wh,    g_wh);
    cudaGetSymbolAddress((void**)&wl,    g_wl);
    cudaGetSymbolAddress((void**)&cqkvh, g_cqkvh);
    cudaGetSymbolAddress((void**)&cqkvl, g_cqkvl);
    cudaGetSymbolAddress((void**)&qh,    g_qh);
    cudaGetSymbolAddress((void**)&ql,    g_ql);
    cudaGetSymbolAddress((void**)&kh,    g_kh);
    cudaGetSymbolAddress((void**)&kl,    g_kl);
    cudaGetSymbolAddress((void**)&vh,    g_vh);
    cudaGetSymbolAddress((void**)&vl,    g_vl);
    cudaGetSymbolAddress((void**)&oh,    g_oh);
    cudaGetSymbolAddress((void**)&ol,    g_ol);
    cudaGetSymbolAddress((void**)&qr,    g_qr);
    cudaGetSymbolAddress((void**)&cc,    g_cc);

    cudaFuncSetAttribute(gemm_mma<true , false, true >,
                         cudaFuncAttributeMaxDynamicSharedMemorySize, GEMM_SMEM);
    cudaFuncSetAttribute(gemm_mma<false, true , false>,
                         cudaFuncAttributeMaxDynamicSharedMemorySize, GEMM_SMEM);
    cudaFuncSetAttribute(gemm_mma<false, false, true >,
                         cudaFuncAttributeMaxDynamicSharedMemorySize, GEMM_SMEM);
    cudaFuncSetAttribute(attn_mma,
                         cudaFuncAttributeMaxDynamicSharedMemorySize, ATTN_SMEM);

    auto cvt = [&](const float* src, __nv_bfloat16* h, __nv_bfloat16* l, size_t n) {
        int n4 = (int)(n / 4);
        cvt_planes<<<(n4 + 255) / 256, 256>>>(src, h, l, n4);
    };
    cvt(x,     xh,           xl,           (size_t)M * 2048);
    cvt(CQ_w,  wh + OFF_Q,   wl + OFF_Q,   512 * 2048);
    cvt(CKV_w, wh + OFF_KV,  wl + OFF_KV,  512 * 2048);
    cvt(CQR_w, wh + OFF_QR,  wl + OFF_QR,  128 * 2048);
    cvt(CKR_w, wh + OFF_KR,  wl + OFF_KR,  128 * 2048);
    cvt(CQC_w, wh + OFF_QC,  wl + OFF_QC,  384 * 512);
    cvt(CKC_w, wh + OFF_KC,  wl + OFF_KC,  384 * 512);
    cvt(CV_w,  wh + OFF_V,   wl + OFF_V,   512 * 512);
    cvt(OUT_w, wh + OFF_OUT, wl + OFF_OUT, 2048 * 512);

    dim3 blk(256);
    const int GY = M / 128;   // 64

    // (1) cq/ckv planes = gelu(x@W^T+b)
    gemm_mma<true , false, true ><<<dim3(4, GY, 2), blk, GEMM_SMEM>>>(
        xh, xl, xh, xl,
        wh + OFF_Q, wl + OFF_Q, wh + OFF_KV, wl + OFF_KV,
        CQ_b, CKV_b,
        nullptr, nullptr,
        cqkvh, cqkvl, cqkvh + 512, cqkvl + 512,
        512, EMBED, EMBED, 0, 1024);

    // (2) cqr/ckr (fp32)
    gemm_mma<false, true , false><<<dim3(1, GY, 2), blk, GEMM_SMEM>>>(
        xh, xl, xh, xl,
        wh + OFF_QR, wl + OFF_QR, wh + OFF_KR, wl + OFF_KR,
        CQR_b, CKR_b,
        qr, qr + 128,
        nullptr, nullptr, nullptr, nullptr,
        128, EMBED, EMBED, 256, 0);

    // (3) cqc/ckc (fp32)
    gemm_mma<false, true , false><<<dim3(3, GY, 2), blk, GEMM_SMEM>>>(
        cqkvh, cqkvl, cqkvh + 512, cqkvl + 512,
        wh + OFF_QC, wl + OFF_QC, wh + OFF_KC, wl + OFF_KC,
        CQC_b, CKC_b,
        cc, cc + (size_t)M * DCC,
        nullptr, nullptr, nullptr, nullptr,
        DCC, DC, 1024, DCC, 0);

    // (4) V planes = ckv @ CV^T + b
    gemm_mma<false, false, true ><<<dim3(4, GY, 1), blk, GEMM_SMEM>>>(
        cqkvh + 512, cqkvl + 512, cqkvh + 512, cqkvl + 512,
        wh + OFF_V, wl + OFF_V, wh + OFF_V, wl + OFF_V,
        CV_b, CV_b,
        nullptr, nullptr,
        vh, vl, vh, vl,
        DC, DC, 1024, 0, DC);

    // Q/K planes (concat + rope + gelu; Q pre-scaled by 1/8)
    int npair = M * 256;
    int nblk  = (npair + 255) / 256;
    build_qk_planes<<<nblk, 256>>>(cc, qr, 0, qh, ql, 0.125f);
    build_qk_planes<<<nblk, 256>>>(cc + (size_t)M * DCC, qr, 128, kh, kl, 1.0f);

    // causal flash attention -> O planes
    attn_mma<<<dim3(S/128, H, B), blk, ATTN_SMEM>>>(qh, ql, kh, kl, vh, vl, oh, ol);

    // (5) out = O @ OUT^T + b (fp32)
    gemm_mma<false, true , false><<<dim3(16, GY, 1), blk, GEMM_SMEM>>>(
        oh, ol, oh, ol,
        wh + OFF_OUT, wl + OFF_OUT, wh + OFF_OUT, wl + OFF_OUT,
        OUT_b, OUT_b,
        out, out,
        nullptr, nullptr, nullptr, nullptr,
        EMBED, DC, DC, EMBED, 0);
}